// round 11
// baseline (speedup 1.0000x reference)
#include <cuda_runtime.h>

#define BATCH 32
#define NCH   4
#define HH    512
#define WW    512
#define PLANE (HH*WW)          /* 262144 */
#define NSTEPS 8
#define D_SCALE 0.2f
#define RHO_SCALE 0.1f
#define FULLM 0xffffffffu

// Ping-pong scratch for the evolving channel-0 field (2 x 32 MiB).
__device__ float g_buf0[BATCH * PLANE];
__device__ float g_buf1[BATCH * PLANE];
// Sums at even steps 0,2,4,6,8: slot k = state entering fused kernel k.
__device__ float g_sum0[5 * BATCH];
__device__ float g_sumsq[5 * BATCH];
// Constant sums of channels 1..3 (index (c-1)*BATCH + b).
__device__ float g_sumc[3 * BATCH];

__global__ void zero_sums_kernel() {
    int i = threadIdx.x;
    if (i < 5 * BATCH) { g_sum0[i] = 0.0f; g_sumsq[i] = 0.0f; }
    if (i < 3 * BATCH) g_sumc[i] = 0.0f;
}

// Copy channels 1..3 input->output; reduce sums (and sumsq for ch0).
__global__ void init_kernel(const float* __restrict__ x, float* __restrict__ out) {
    const int p = blockIdx.y;            // plane id = b*4 + c
    const int b = p >> 2;
    const int c = p & 3;
    const int i = blockIdx.x * blockDim.x + threadIdx.x;

    const float4* src = (const float4*)(x + (size_t)p * PLANE);
    float4 v = src[i];
    if (c != 0) {
        ((float4*)(out + (size_t)p * PLANE))[i] = v;
    }
    float s  = (v.x + v.y) + (v.z + v.w);
    float s2 = (v.x * v.x + v.y * v.y) + (v.z * v.z + v.w * v.w);

    #pragma unroll
    for (int o = 16; o > 0; o >>= 1) {
        s  += __shfl_down_sync(FULLM, s,  o);
        s2 += __shfl_down_sync(FULLM, s2, o);
    }
    __shared__ float ws[8], ws2[8];
    const int lane = threadIdx.x & 31;
    const int w    = threadIdx.x >> 5;
    if (lane == 0) { ws[w] = s; ws2[w] = s2; }
    __syncthreads();
    if (w == 0) {
        s  = (lane < 8) ? ws[lane]  : 0.0f;
        s2 = (lane < 8) ? ws2[lane] : 0.0f;
        #pragma unroll
        for (int o = 4; o > 0; o >>= 1) {
            s  += __shfl_down_sync(0x000000ffu, s,  o);
            s2 += __shfl_down_sync(0x000000ffu, s2, o);
        }
        if (lane == 0) {
            if (c == 0) {
                atomicAdd(&g_sum0[b],  s);
                atomicAdd(&g_sumsq[b], s2);
            } else {
                atomicAdd(&g_sumc[(c - 1) * BATCH + b], s);
            }
        }
    }
}

// TWO fused reaction-diffusion steps, warp-private (no smem staging).
//   sum_{s+1} = sum_s + rho_s*(sum_s - sumsq_s)   (periodic: sum(lap)=0)
// Warp = (chunk of 128 cols, strip of 8 output rows). Row loads are
// software-pipelined (preload 5, prefetch 1/iter, live window ~6 float4)
// so the 64-reg cap (launch_bounds minBlocks=4) is met without spills.
// grid = (HH/16, BATCH) = (32, 32), block = 256 (8 warps: 4 chunks x 2 grps).
__global__ __launch_bounds__(256, 4) void fused2_kernel(
        const float* __restrict__ src, int src_bstride,
        float* __restrict__ dst, int dst_bstride,
        const float* __restrict__ Wm,
        const float* __restrict__ bias,
        const int* __restrict__ t, int s) {
    const int b    = blockIdx.y;
    const int tid  = threadIdx.x;
    const int lane = tid & 31;
    const int wid  = tid >> 5;
    const int chunk = wid & 3;
    const int grp   = wid >> 2;                 // 0 or 1
    const int y0    = blockIdx.x * 16 + grp * 8;

    const float* __restrict__ u = src + (size_t)b * src_bstride;
    float* __restrict__ v       = dst + (size_t)b * dst_bstride;

    const int xb  = chunk << 7;
    const int x4  = xb + (lane << 2);
    const int xl2 = (xb + WW - 2) & (WW - 1);   // cols xb-2, xb-1 (float2)
    const int xr2 = (xb + 128) & (WW - 1);      // cols xb+128, xb+129 (float2)

    // ---- Edge data for 12 rows (lanes 0..11), issued first ----
    float2 eL = make_float2(0.f, 0.f), eR = make_float2(0.f, 0.f);
    float sxb = 0.0f, sxbr = 0.0f;
    if (lane < 12) {
        const int row = ((y0 - 2 + lane) & (HH - 1)) << 9;
        eL   = *(const float2*)(u + row + xl2);   // (xb-2, xb-1)
        eR   = *(const float2*)(u + row + xr2);   // (xb+128, xb+129)
        sxb  = u[row + xb];                       // col xb
        sxbr = u[row + xb + 127];                 // col xb+127
    }

    // ---- Software-pipelined main-row loads: preload 5 of 12 ----
    float4 R[12];
    #pragma unroll
    for (int k = 0; k < 5; k++)
        R[k] = *(const float4*)(u + (((y0 - 2 + k) & (HH - 1)) << 9) + x4);

    // ---- D/rho for both sub-steps (overlaps loads) ----
    const int slot = s >> 1;
    const float inv = 1.0f / (float)PLANE;
    const float sum_s = g_sum0[slot * BATCH + b];
    const float ssq_s = g_sumsq[slot * BATCH + b];
    const float f1 = g_sumc[0 * BATCH + b] * inv;
    const float f2 = g_sumc[1 * BATCH + b] * inv;
    const float f3 = g_sumc[2 * BATCH + b] * inv;
    const float zc0 = f1 * Wm[2] + f2 * Wm[4] + f3 * Wm[6] + bias[0];
    const float zc1 = f1 * Wm[3] + f2 * Wm[5] + f3 * Wm[7] + bias[1];
    const int tb = t[b];

    const float f0 = sum_s * inv;
    float D0 = D_SCALE   / (1.0f + __expf(-(f0 * Wm[0] + zc0)));
    float r0 = RHO_SCALE / (1.0f + __expf(-(f0 * Wm[1] + zc1)));
    if (tb <= s) { D0 = 0.0f; r0 = 0.0f; }

    const float sum_n = sum_s + r0 * (sum_s - ssq_s);   // exact (periodic BC)
    const float f0n = sum_n * inv;
    float D1 = D_SCALE   / (1.0f + __expf(-(f0n * Wm[0] + zc0)));
    float r1 = RHO_SCALE / (1.0f + __expf(-(f0n * Wm[1] + zc1)));
    if (tb <= s + 1) { D1 = 0.0f; r1 = 0.0f; }

    // ---- Edge intermediates: lane i = row y0-2+i (valid i=1..10) ----
    float iLv, iRv;
    {
        float up = __shfl_up_sync(FULLM, eL.y, 1);
        float dn = __shfl_down_sync(FULLM, eL.y, 1);
        iLv = fmaf(D0, up + dn + eL.x + sxb - 4.0f * eL.y,
                   fmaf(r0 * eL.y, 1.0f - eL.y, eL.y));
        up = __shfl_up_sync(FULLM, eR.x, 1);
        dn = __shfl_down_sync(FULLM, eR.x, 1);
        iRv = fmaf(D0, up + dn + sxbr + eR.y - 4.0f * eR.x,
                   fmaf(r0 * eR.x, 1.0f - eR.x, eR.x));
    }

    // ---- Main loop: intermediates m=0..9 (rows y0-1..y0+8), outputs j=m-2 ----
    float4 I[3];
    float acc = 0.0f, acc2 = 0.0f;
    #pragma unroll
    for (int m = 0; m < 10; m++) {
        // prefetch row m+5 (keeps ~5 loads in flight, small live window)
        if (m + 5 < 12)
            R[m + 5] = *(const float4*)(u + (((y0 + 3 + m) & (HH - 1)) << 9) + x4);

        const float4 P = R[m], C = R[m + 1], N = R[m + 2];
        const float lein = __shfl_sync(FULLM, eL.y, m + 1);
        const float riin = __shfl_sync(FULLM, eR.x, m + 1);
        float le = __shfl_up_sync(FULLM, C.w, 1);
        float ri = __shfl_down_sync(FULLM, C.x, 1);
        if (lane == 0)  le = lein;
        if (lane == 31) ri = riin;

        float4 o;
        o.x = fmaf(D0, P.x + N.x + le  + C.y - 4.0f * C.x, fmaf(r0 * C.x, 1.0f - C.x, C.x));
        o.y = fmaf(D0, P.y + N.y + C.x + C.z - 4.0f * C.y, fmaf(r0 * C.y, 1.0f - C.y, C.y));
        o.z = fmaf(D0, P.z + N.z + C.y + C.w - 4.0f * C.z, fmaf(r0 * C.z, 1.0f - C.z, C.z));
        o.w = fmaf(D0, P.w + N.w + C.z + ri  - 4.0f * C.w, fmaf(r0 * C.w, 1.0f - C.w, C.w));
        I[m % 3] = o;

        if (m >= 2) {
            const int j = m - 2;                      // output row y0+j
            const float4 Pm = I[j % 3];               // row y0+j-1
            const float4 Cm = I[(j + 1) % 3];         // row y0+j
            const float4 Nm = I[(j + 2) % 3];         // row y0+j+1
            const float leo = __shfl_sync(FULLM, iLv, j + 2);
            const float rio = __shfl_sync(FULLM, iRv, j + 2);
            float le2 = __shfl_up_sync(FULLM, Cm.w, 1);
            float ri2 = __shfl_down_sync(FULLM, Cm.x, 1);
            if (lane == 0)  le2 = leo;
            if (lane == 31) ri2 = rio;

            float4 q;
            q.x = fmaf(D1, Pm.x + Nm.x + le2 + Cm.y - 4.0f * Cm.x, fmaf(r1 * Cm.x, 1.0f - Cm.x, Cm.x));
            q.y = fmaf(D1, Pm.y + Nm.y + Cm.x + Cm.z - 4.0f * Cm.y, fmaf(r1 * Cm.y, 1.0f - Cm.y, Cm.y));
            q.z = fmaf(D1, Pm.z + Nm.z + Cm.y + Cm.w - 4.0f * Cm.z, fmaf(r1 * Cm.z, 1.0f - Cm.z, Cm.z));
            q.w = fmaf(D1, Pm.w + Nm.w + Cm.z + ri2  - 4.0f * Cm.w, fmaf(r1 * Cm.w, 1.0f - Cm.w, Cm.w));

            *(float4*)(v + ((y0 + j) << 9) + x4) = q;
            acc  += (q.x + q.y) + (q.z + q.w);
            acc2 += (q.x * q.x + q.y * q.y) + (q.z * q.z + q.w * q.w);
        }
    }

    // ---- Block reduction of sum & sumsq, one atomic pair per block ----
    #pragma unroll
    for (int o = 16; o > 0; o >>= 1) {
        acc  += __shfl_down_sync(FULLM, acc,  o);
        acc2 += __shfl_down_sync(FULLM, acc2, o);
    }
    __shared__ float ws[8], ws2[8];
    if (lane == 0) { ws[wid] = acc; ws2[wid] = acc2; }
    __syncthreads();
    if (wid == 0) {
        acc  = (lane < 8) ? ws[lane]  : 0.0f;
        acc2 = (lane < 8) ? ws2[lane] : 0.0f;
        #pragma unroll
        for (int o = 4; o > 0; o >>= 1) {
            acc  += __shfl_down_sync(0x000000ffu, acc,  o);
            acc2 += __shfl_down_sync(0x000000ffu, acc2, o);
        }
        if (lane == 0) {
            atomicAdd(&g_sum0[(slot + 1) * BATCH + b],  acc);
            atomicAdd(&g_sumsq[(slot + 1) * BATCH + b], acc2);
        }
    }
}

extern "C" void kernel_launch(void* const* d_in, const int* in_sizes, int n_in,
                              void* d_out, int out_size) {
    const float* x  = (const float*)d_in[0];   // (32,4,512,512)
    const float* Wm = (const float*)d_in[1];   // (4,2)
    const float* bb = (const float*)d_in[2];   // (2,)
    const int*   t  = (const int*)d_in[3];     // (32,)
    float* out = (float*)d_out;

    zero_sums_kernel<<<1, 256>>>();

    // Copy ch1..3, reduce per-(b,c) sums (+ sumsq for ch0).
    init_kernel<<<dim3(PLANE / 4 / 256, BATCH * NCH), dim3(256)>>>(x, out);

    float* bufA; float* bufB;
    cudaGetSymbolAddress((void**)&bufA, g_buf0);
    cudaGetSymbolAddress((void**)&bufB, g_buf1);

    const dim3 fgrid(HH / 16, BATCH);   // (32, 32) = 1024 blocks
    // 4 fused kernels: steps (0,1), (2,3), (4,5), (6,7)
    for (int k = 0; k < 4; k++) {
        const int s = 2 * k;
        const float* src;  int sstride;
        float*       dst;  int dstride;
        if (k == 0) { src = x;  sstride = NCH * PLANE; }
        else        { src = (k & 1) ? bufA : bufB; sstride = PLANE; }
        if (k == 3) { dst = out; dstride = NCH * PLANE; }
        else        { dst = (k & 1) ? bufB : bufA; dstride = PLANE; }
        fused2_kernel<<<fgrid, 256>>>(src, sstride, dst, dstride, Wm, bb, t, s);
    }
}